// round 3
// baseline (speedup 1.0000x reference)
#include <cuda_runtime.h>
#include <cuda_bf16.h>
#include <math.h>
#include <stdint.h>

// Problem constants
#define BATCH   512
#define NNODES  256
#define MROWS   (BATCH * NNODES)     // 131072
#define FEAT_IN 512                  // LN dim
#define GLOB_D  64
#define KIN     576                  // FEAT_IN + GLOB_D
#define FHID    1024
#define AHID    256
#define FOUT    256
#define NHEADS  4
#define HEADDIM 64
#define LN_EPS  1e-5f

// ---------------------------------------------------------------------------
// Scratch (module-scope device globals; no runtime allocation)
// ---------------------------------------------------------------------------
__device__ float g_inp[(size_t)MROWS * KIN];     // 302 MB
__device__ float g_hid[(size_t)MROWS * FHID];    // 512 MB
__device__ float g_ah [(size_t)MROWS * AHID];    // 128 MB
__device__ float g_scores[(size_t)MROWS * NHEADS];
__device__ float g_w     [(size_t)MROWS * NHEADS];

// ---------------------------------------------------------------------------
// Utilities
// ---------------------------------------------------------------------------
__device__ __forceinline__ float warp_sum(float v) {
    #pragma unroll
    for (int o = 16; o > 0; o >>= 1) v += __shfl_xor_sync(0xffffffffu, v, o);
    return v;
}

// ---------------------------------------------------------------------------
// Kernel 1: LayerNorm(concat(nodes, pooled_edges)) || globs  ->  g_inp [M,576]
// one block (128 threads) per row
// ---------------------------------------------------------------------------
__global__ void prep_kernel(const float* __restrict__ nodes,
                            const float* __restrict__ pe,
                            const float* __restrict__ globs,
                            const float* __restrict__ ln_g,
                            const float* __restrict__ ln_b,
                            float* __restrict__ inp)
{
    const int row = blockIdx.x;          // 0..131071
    const int t   = threadIdx.x;         // 0..127
    const int b   = row >> 8;

    float4 v = (t < 64)
        ? ((const float4*)nodes)[(size_t)row * 64 + t]
        : ((const float4*)pe)   [(size_t)row * 64 + (t - 64)];

    float s  = v.x + v.y + v.z + v.w;
    float sq = v.x*v.x + v.y*v.y + v.z*v.z + v.w*v.w;

    __shared__ float ssum[4], ssq[4];
    __shared__ float s_mu, s_rstd;
    const int lane = t & 31, wid = t >> 5;
    float ws = warp_sum(s), wq = warp_sum(sq);
    if (lane == 0) { ssum[wid] = ws; ssq[wid] = wq; }
    __syncthreads();
    if (t == 0) {
        float S = ssum[0] + ssum[1] + ssum[2] + ssum[3];
        float Q = ssq[0]  + ssq[1]  + ssq[2]  + ssq[3];
        float mu  = S * (1.0f / FEAT_IN);
        float var = Q * (1.0f / FEAT_IN) - mu * mu;
        s_mu   = mu;
        s_rstd = rsqrtf(var + LN_EPS);
    }
    __syncthreads();
    const float mu = s_mu, rstd = s_rstd;

    float4 g4 = ((const float4*)ln_g)[t];
    float4 b4 = ((const float4*)ln_b)[t];
    float4 o;
    o.x = (v.x - mu) * rstd * g4.x + b4.x;
    o.y = (v.y - mu) * rstd * g4.y + b4.y;
    o.z = (v.z - mu) * rstd * g4.z + b4.z;
    o.w = (v.w - mu) * rstd * g4.w + b4.w;
    *(float4*)&inp[(size_t)row * KIN + t * 4] = o;

    if (t < GLOB_D)
        inp[(size_t)row * KIN + FEAT_IN + t] = globs[b * GLOB_D + t];
}

// ---------------------------------------------------------------------------
// SGEMM: C[M,N] = A[M,K] @ W[K,N] (+bias, epilogue)
// 128x128 block tile, BK=32, 256 threads, 8x8 microtile
// MODE 0: SiLU -> C (scratch)
// MODE 1: bias, zero-if-masked, +residual -> C  (new_nodes epilogue, N must be 256)
// ---------------------------------------------------------------------------
#define BM 128
#define BN 128
#define BK 32

template<int MODE>
__global__ __launch_bounds__(256) void sgemm_kernel(
    const float* __restrict__ A, const float* __restrict__ W,
    const float* __restrict__ bias, float* __restrict__ C,
    int M, int N, int K,
    const float* __restrict__ residual, const int* __restrict__ mask)
{
    __shared__ float As[BK][BM];
    __shared__ float Bs[BK][BN];

    const int row0 = blockIdx.y * BM;
    const int col0 = blockIdx.x * BN;
    const int tid  = threadIdx.x;
    const int tx   = tid & 15;          // 0..15 -> columns
    const int ty   = tid >> 4;          // 0..15 -> rows

    // A-tile load mapping: (128 rows x 8 float4) = 1024 float4 / 256 thr = 4 each
    const int ar = tid >> 3;            // 0..31
    const int ac = (tid & 7) * 4;       // 0,4,..,28
    // B-tile load mapping: (32 rows x 32 float4) = 1024 float4 / 256 thr = 4 each
    const int br = tid >> 5;            // 0..7
    const int bc = (tid & 31) * 4;      // 0..124

    float acc[8][8];
    #pragma unroll
    for (int m = 0; m < 8; m++)
        #pragma unroll
        for (int n = 0; n < 8; n++) acc[m][n] = 0.0f;

    for (int kk = 0; kk < K; kk += BK) {
        #pragma unroll
        for (int i = 0; i < 4; i++) {
            int r = ar + i * 32;
            float4 v = *(const float4*)&A[(size_t)(row0 + r) * K + kk + ac];
            As[ac + 0][r] = v.x; As[ac + 1][r] = v.y;
            As[ac + 2][r] = v.z; As[ac + 3][r] = v.w;
        }
        #pragma unroll
        for (int i = 0; i < 4; i++) {
            int r = br + i * 8;
            *(float4*)&Bs[r][bc] = *(const float4*)&W[(size_t)(kk + r) * N + col0 + bc];
        }
        __syncthreads();

        #pragma unroll
        for (int k = 0; k < BK; k++) {
            float a[8], bv[8];
            #pragma unroll
            for (int m = 0; m < 8; m++) a[m]  = As[k][ty * 8 + m];
            #pragma unroll
            for (int n = 0; n < 8; n++) bv[n] = Bs[k][tx * 8 + n];
            #pragma unroll
            for (int m = 0; m < 8; m++)
                #pragma unroll
                for (int n = 0; n < 8; n++)
                    acc[m][n] = fmaf(a[m], bv[n], acc[m][n]);
        }
        __syncthreads();
    }

    const int ccol = col0 + tx * 8;
    #pragma unroll
    for (int m = 0; m < 8; m++) {
        const int r = row0 + ty * 8 + m;
        int mv = 1;
        if (MODE == 1) mv = mask[r];
        #pragma unroll
        for (int nv = 0; nv < 2; nv++) {
            float4 o;
            float* a = &acc[m][nv * 4];
            const int c = ccol + nv * 4;
            if (MODE == 0) {
                float v0 = a[0] + bias[c + 0];
                float v1 = a[1] + bias[c + 1];
                float v2 = a[2] + bias[c + 2];
                float v3 = a[3] + bias[c + 3];
                o.x = v0 / (1.0f + __expf(-v0));
                o.y = v1 / (1.0f + __expf(-v1));
                o.z = v2 / (1.0f + __expf(-v2));
                o.w = v3 / (1.0f + __expf(-v3));
            } else {
                float v0 = a[0] + bias[c + 0];
                float v1 = a[1] + bias[c + 1];
                float v2 = a[2] + bias[c + 2];
                float v3 = a[3] + bias[c + 3];
                if (!mv) { v0 = 0.f; v1 = 0.f; v2 = 0.f; v3 = 0.f; }
                o.x = v0 + residual[(size_t)r * FOUT + c + 0];
                o.y = v1 + residual[(size_t)r * FOUT + c + 1];
                o.z = v2 + residual[(size_t)r * FOUT + c + 2];
                o.w = v3 + residual[(size_t)r * FOUT + c + 3];
            }
            *(float4*)&C[(size_t)r * N + c] = o;
        }
    }
}

// ---------------------------------------------------------------------------
// Attention head projection: scores[M,4] = g_ah[M,256] @ aw2[256,4] + ab2
// one warp per row
// ---------------------------------------------------------------------------
__global__ void attn2_kernel(const float* __restrict__ ah,
                             const float* __restrict__ aw2,
                             const float* __restrict__ ab2,
                             float* __restrict__ scores)
{
    const int warp = (blockIdx.x * blockDim.x + threadIdx.x) >> 5;
    const int lane = threadIdx.x & 31;
    if (warp >= MROWS) return;
    const float* a = ah + (size_t)warp * AHID;
    float a0 = 0.f, a1 = 0.f, a2 = 0.f, a3 = 0.f;
    #pragma unroll
    for (int i = 0; i < AHID / 32; i++) {
        int k = lane + i * 32;
        float av = a[k];
        float4 wv = ((const float4*)aw2)[k];
        a0 = fmaf(av, wv.x, a0); a1 = fmaf(av, wv.y, a1);
        a2 = fmaf(av, wv.z, a2); a3 = fmaf(av, wv.w, a3);
    }
    a0 = warp_sum(a0); a1 = warp_sum(a1); a2 = warp_sum(a2); a3 = warp_sum(a3);
    if (lane == 0) {
        float4 o = make_float4(a0 + ab2[0], a1 + ab2[1], a2 + ab2[2], a3 + ab2[3]);
        ((float4*)scores)[warp] = o;
    }
}

// ---------------------------------------------------------------------------
// Masked softmax over nodes, per (graph, head). one block (256 thr) per graph.
// ---------------------------------------------------------------------------
__global__ void softmax_kernel(const float* __restrict__ scores,
                               const int* __restrict__ mask,
                               float* __restrict__ w)
{
    const int b = blockIdx.x;
    const int n = threadIdx.x;
    const int idx = b * NNODES + n;
    const float NEG = -INFINITY;
    const float inv_scale = 1.0f / 16.0f;   // 1/sqrt(256)

    float4 s = ((const float4*)scores)[idx];
    const bool valid = mask[idx] != 0;
    float v0 = valid ? s.x * inv_scale : NEG;
    float v1 = valid ? s.y * inv_scale : NEG;
    float v2 = valid ? s.z * inv_scale : NEG;
    float v3 = valid ? s.w * inv_scale : NEG;

    __shared__ float4 red[NNODES];
    red[n] = make_float4(v0, v1, v2, v3);
    __syncthreads();
    for (int off = 128; off > 0; off >>= 1) {
        if (n < off) {
            float4 a = red[n], c = red[n + off];
            red[n] = make_float4(fmaxf(a.x, c.x), fmaxf(a.y, c.y),
                                 fmaxf(a.z, c.z), fmaxf(a.w, c.w));
        }
        __syncthreads();
    }
    float4 mx = red[0];
    __syncthreads();

    float e0 = valid ? __expf(v0 - mx.x) : 0.f;
    float e1 = valid ? __expf(v1 - mx.y) : 0.f;
    float e2 = valid ? __expf(v2 - mx.z) : 0.f;
    float e3 = valid ? __expf(v3 - mx.w) : 0.f;

    red[n] = make_float4(e0, e1, e2, e3);
    __syncthreads();
    for (int off = 128; off > 0; off >>= 1) {
        if (n < off) {
            float4 a = red[n], c = red[n + off];
            red[n] = make_float4(a.x + c.x, a.y + c.y, a.z + c.z, a.w + c.w);
        }
        __syncthreads();
    }
    float4 sm = red[0];

    float4 o = make_float4(e0 / sm.x, e1 / sm.y, e2 / sm.z, e3 / sm.w);
    ((float4*)w)[idx] = o;
}

// ---------------------------------------------------------------------------
// Attention pooling: pooled[b,c] = sum_n new_nodes[b,n,c] * w[b,n,c/64]
// one block (256 thr) per graph; thread = output channel
// ---------------------------------------------------------------------------
__global__ void pool_kernel(const float* __restrict__ newn,
                            const float* __restrict__ w,
                            float* __restrict__ pooled)
{
    const int b = blockIdx.x;
    const int c = threadIdx.x;
    __shared__ float ws[NNODES * NHEADS];
    ((float4*)ws)[c] = ((const float4*)(w + (size_t)b * NNODES * NHEADS))[c];
    __syncthreads();

    const int h = c >> 6;
    const float* base = newn + (size_t)b * NNODES * FOUT + c;
    float acc = 0.f;
    #pragma unroll 8
    for (int n = 0; n < NNODES; n++)
        acc = fmaf(base[(size_t)n * FOUT], ws[n * NHEADS + h], acc);
    pooled[b * FOUT + c] = acc;
}

// ---------------------------------------------------------------------------
// Launch
// ---------------------------------------------------------------------------
extern "C" void kernel_launch(void* const* d_in, const int* in_sizes, int n_in,
                              void* d_out, int out_size)
{
    const float* nodes = (const float*)d_in[0];
    const float* pe    = (const float*)d_in[1];
    const int*   mask  = (const int*)d_in[2];
    const float* globs = (const float*)d_in[3];
    const float* ln_g  = (const float*)d_in[4];
    const float* ln_b  = (const float*)d_in[5];
    const float* fw1   = (const float*)d_in[6];
    const float* fb1   = (const float*)d_in[7];
    const float* fw2   = (const float*)d_in[8];
    const float* fb2   = (const float*)d_in[9];
    const float* aw1   = (const float*)d_in[10];
    const float* ab1   = (const float*)d_in[11];
    const float* aw2   = (const float*)d_in[12];
    const float* ab2   = (const float*)d_in[13];

    float* out_nodes  = (float*)d_out;                                // [M,256]
    float* out_pooled = out_nodes + (size_t)MROWS * FOUT;             // [B,256]

    float *p_inp, *p_hid, *p_ah, *p_scores, *p_w;
    cudaGetSymbolAddress((void**)&p_inp,    g_inp);
    cudaGetSymbolAddress((void**)&p_hid,    g_hid);
    cudaGetSymbolAddress((void**)&p_ah,     g_ah);
    cudaGetSymbolAddress((void**)&p_scores, g_scores);
    cudaGetSymbolAddress((void**)&p_w,      g_w);

    // 1) LN + concat -> inp [M,576]
    prep_kernel<<<MROWS, 128>>>(nodes, pe, globs, ln_g, ln_b, p_inp);

    // 2) feature hidden: silu(inp @ fw1 + fb1) -> g_hid [M,1024]
    sgemm_kernel<0><<<dim3(FHID / BN, MROWS / BM), 256>>>(
        p_inp, fw1, fb1, p_hid, MROWS, FHID, KIN, nullptr, nullptr);

    // 3) attn hidden: silu(inp @ aw1 + ab1) -> g_ah [M,256]
    sgemm_kernel<0><<<dim3(AHID / BN, MROWS / BM), 256>>>(
        p_inp, aw1, ab1, p_ah, MROWS, AHID, KIN, nullptr, nullptr);

    // 4) head scores [M,4]
    attn2_kernel<<<MROWS / 8, 256>>>(p_ah, aw2, ab2, p_scores);

    // 5) masked softmax over nodes -> g_w [M,4]
    softmax_kernel<<<BATCH, NNODES>>>(p_scores, mask, p_w);

    // 6) feature out + mask + residual -> new_nodes (d_out)
    sgemm_kernel<1><<<dim3(FOUT / BN, MROWS / BM), 256>>>(
        p_hid, fw2, fb2, out_nodes, MROWS, FOUT, FHID, nodes, mask);

    // 7) attention pooling -> pooled (d_out tail)
    pool_kernel<<<BATCH, 256>>>(out_nodes, p_w, out_pooled);
}

// round 6
// speedup vs baseline: 5.0124x; 5.0124x over previous
#include <cuda_runtime.h>
#include <cuda_fp16.h>
#include <math.h>
#include <stdint.h>

// Problem constants
#define BATCH   512
#define NNODES  256
#define MROWS   (BATCH * NNODES)     // 131072
#define FEAT_IN 512
#define GLOB_D  64
#define KIN     576
#define FHID    1024
#define AHID    256
#define FOUT    256
#define NHEADS  4
#define LN_EPS  1e-5f

// ---------------------------------------------------------------------------
// Scratch (device globals; no runtime allocation)
// ---------------------------------------------------------------------------
__device__ __half g_inp[(size_t)MROWS * KIN];          // fp16 LN output [M,576]
__device__ __half g_hid[(size_t)MROWS * FHID];         // fp16 silu hidden [M,1024]
__device__ float  g_ah [(size_t)MROWS * AHID];         // fp32 attn hidden [M,256]
__device__ float  g_scores[(size_t)MROWS * NHEADS];
__device__ float  g_wsm   [(size_t)MROWS * NHEADS];
__device__ __half g_w1t[(size_t)(FHID + AHID) * KIN];  // [1280,576] (fw1||aw1)^T fp16
__device__ __half g_w2t[(size_t)FOUT * FHID];          // [256,1024] fw2^T fp16

// ---------------------------------------------------------------------------
// PTX helpers (baseline ISA: works at compute_103 target)
// ---------------------------------------------------------------------------
__device__ __forceinline__ uint32_t smem_u32(const void* p) {
    uint32_t a;
    asm("{ .reg .u64 t; cvta.to.shared.u64 t, %1; cvt.u32.u64 %0, t; }"
        : "=r"(a) : "l"(p));
    return a;
}

#define CP_ASYNC16(dst, src) \
    asm volatile("cp.async.cg.shared.global [%0], [%1], 16;" \
        :: "r"(dst), "l"(src))
#define CP_COMMIT()  asm volatile("cp.async.commit_group;" ::: "memory")
#define CP_WAIT1()   asm volatile("cp.async.wait_group 1;" ::: "memory")

#define LDSM_X4(r0, r1, r2, r3, addr) \
    asm volatile("ldmatrix.sync.aligned.m8n8.x4.shared.b16 {%0,%1,%2,%3}, [%4];" \
        : "=r"(r0), "=r"(r1), "=r"(r2), "=r"(r3) : "r"(addr))

#define MMA16816(c, a, b) \
    asm volatile("mma.sync.aligned.m16n8k16.row.col.f32.f16.f16.f32 " \
        "{%0,%1,%2,%3}, {%4,%5,%6,%7}, {%8,%9}, {%0,%1,%2,%3};" \
        : "+f"((c)[0]), "+f"((c)[1]), "+f"((c)[2]), "+f"((c)[3]) \
        : "r"((a)[0]), "r"((a)[1]), "r"((a)[2]), "r"((a)[3]), \
          "r"((b)[0]), "r"((b)[1]))

__device__ __forceinline__ float warp_sum(float v) {
    #pragma unroll
    for (int o = 16; o > 0; o >>= 1) v += __shfl_xor_sync(0xffffffffu, v, o);
    return v;
}

__device__ __forceinline__ float silu(float v) {
    return __fdividef(v, 1.0f + __expf(-v));
}

// ---------------------------------------------------------------------------
// Kernel 1: LayerNorm(concat(nodes, pe)) || globs -> g_inp fp16 [M,576]
// ---------------------------------------------------------------------------
__global__ void prep_kernel(const float* __restrict__ nodes,
                            const float* __restrict__ pe,
                            const float* __restrict__ globs,
                            const float* __restrict__ ln_g,
                            const float* __restrict__ ln_b,
                            __half* __restrict__ inp)
{
    const int row = blockIdx.x;
    const int t   = threadIdx.x;          // 0..127
    const int b   = row >> 8;

    float4 v = (t < 64)
        ? ((const float4*)nodes)[(size_t)row * 64 + t]
        : ((const float4*)pe)   [(size_t)row * 64 + (t - 64)];

    float s  = v.x + v.y + v.z + v.w;
    float sq = v.x*v.x + v.y*v.y + v.z*v.z + v.w*v.w;

    __shared__ float ssum[4], ssq[4];
    __shared__ float s_mu, s_rstd;
    const int lane = t & 31, wid = t >> 5;
    float ws = warp_sum(s), wq = warp_sum(sq);
    if (lane == 0) { ssum[wid] = ws; ssq[wid] = wq; }
    __syncthreads();
    if (t == 0) {
        float S = ssum[0] + ssum[1] + ssum[2] + ssum[3];
        float Q = ssq[0]  + ssq[1]  + ssq[2]  + ssq[3];
        float mu  = S * (1.0f / FEAT_IN);
        float var = Q * (1.0f / FEAT_IN) - mu * mu;
        s_mu = mu; s_rstd = rsqrtf(var + LN_EPS);
    }
    __syncthreads();
    const float mu = s_mu, rstd = s_rstd;

    float4 g4 = ((const float4*)ln_g)[t];
    float4 b4 = ((const float4*)ln_b)[t];
    float o0 = (v.x - mu) * rstd * g4.x + b4.x;
    float o1 = (v.y - mu) * rstd * g4.y + b4.y;
    float o2 = (v.z - mu) * rstd * g4.z + b4.z;
    float o3 = (v.w - mu) * rstd * g4.w + b4.w;

    __half* dst = inp + (size_t)row * KIN + t * 4;
    *(__half2*)(dst)     = __floats2half2_rn(o0, o1);
    *(__half2*)(dst + 2) = __floats2half2_rn(o2, o3);

    if (t < GLOB_D)
        inp[(size_t)row * KIN + FEAT_IN + t] = __float2half_rn(globs[b * GLOB_D + t]);
}

// ---------------------------------------------------------------------------
// Weight transpose + fp16 cast: Wt[n,k] = (n<N1 ? W1[k,n] : W2[k,n-N1])
// ---------------------------------------------------------------------------
__global__ void wtrans_kernel(const float* __restrict__ W1, int N1,
                              const float* __restrict__ W2, int N2,
                              int K, __half* __restrict__ Wt)
{
    __shared__ float tile[32][33];
    const int nb = blockIdx.x * 32, kb = blockIdx.y * 32;
    const int tx = threadIdx.x, ty = threadIdx.y;
    const int Ntot = N1 + N2;
    for (int i = ty; i < 32; i += 8) {
        int k = kb + i, n = nb + tx;
        float v = 0.f;
        if (k < K && n < Ntot)
            v = (n < N1) ? W1[(size_t)k * N1 + n] : W2[(size_t)k * N2 + (n - N1)];
        tile[i][tx] = v;
    }
    __syncthreads();
    for (int i = ty; i < 32; i += 8) {
        int n = nb + i, k = kb + tx;
        if (n < Ntot && k < K)
            Wt[(size_t)n * K + k] = __float2half_rn(tile[tx][i]);
    }
}

// ---------------------------------------------------------------------------
// HGEMM via mma.sync m16n8k16: C[M,N] = A[M,K] @ Bt[N,K]^T (+epilogue)
// CTA tile 128x128, BK=32, 3-stage cp.async pipeline, 8 warps (4m x 2n),
// warp tile 32x64. Smem row stride 40 halfs (80B) -> conflict-free ldmatrix.
// MODE 0 (GEMM1): silu(x + bias); ncol<1024 -> fp16 outh[.,1024];
//                 ncol>=1024 -> fp32 outf[.,256] with bias2.
// MODE 1 (GEMM3): x + bias1, zero-if-!mask, +residual -> fp32 outf[.,256].
// ---------------------------------------------------------------------------
#define GSTAGE_B  20480               // (128*40*2) * 2 tiles
#define GSMEM     (3 * GSTAGE_B)      // 61440

template<int MODE>
__global__ __launch_bounds__(256) void gemm_mma(
    const __half* __restrict__ A, const __half* __restrict__ Bt, int K,
    const float* __restrict__ bias1, const float* __restrict__ bias2,
    __half* __restrict__ outh, float* __restrict__ outf,
    const int* __restrict__ mask, const float* __restrict__ residual)
{
    extern __shared__ char smem[];
    const uint32_t sbase = smem_u32(smem);
    const int tid    = threadIdx.x;
    const int wid    = tid >> 5;
    const int lane   = tid & 31;
    const int warp_m = wid & 3;        // 4 groups of 32 rows
    const int warp_n = wid >> 2;       // 2 groups of 64 cols
    const int row0   = blockIdx.y * 128;
    const int col0   = blockIdx.x * 128;
    const int iters  = K >> 5;

    // per-thread cp.async source/dest mapping (2 x 16B per tile per stage)
    const int ldr = tid >> 2;              // 0..63  (row base; +64 for i=1)
    const int ldk = (tid & 3) * 8;         // k-offset in halfs (16B units)

    float acc[2][8][4];
    #pragma unroll
    for (int mt = 0; mt < 2; mt++)
        #pragma unroll
        for (int nt = 0; nt < 8; nt++)
            #pragma unroll
            for (int j = 0; j < 4; j++) acc[mt][nt][j] = 0.f;

    // ldmatrix lane-derived offsets
    const int lm = lane & 15, lq = lane >> 4;
    const uint32_t aoff = ((warp_m * 32 + lm) * 40 + lq * 8) * 2;
    const int bn = (lane >> 4) * 8 + (lane & 7);
    const int bk = ((lane >> 3) & 1) * 8;
    const uint32_t boff = ((warp_n * 64 + bn) * 40 + bk) * 2;

    auto load_stage = [&](int s, int kk) {
        const uint32_t dA = sbase + s * GSTAGE_B;
        const uint32_t dB = dA + 10240;
        #pragma unroll
        for (int i = 0; i < 2; i++) {
            const int r = ldr + i * 64;
            const uint32_t soff = (r * 40 + ldk) * 2;
            CP_ASYNC16(dA + soff, &A [(size_t)(row0 + r) * K + kk + ldk]);
            CP_ASYNC16(dB + soff, &Bt[(size_t)(col0 + r) * K + kk + ldk]);
        }
    };

    load_stage(0, 0);
    CP_COMMIT();
    if (iters > 1) load_stage(1, 32);
    CP_COMMIT();

    for (int i = 0; i < iters; i++) {
        CP_WAIT1();
        __syncthreads();
        if (i + 2 < iters) load_stage((i + 2) % 3, (i + 2) * 32);
        CP_COMMIT();

        const int s = i % 3;
        const uint32_t sA = sbase + s * GSTAGE_B;
        const uint32_t sB = sA + 10240;

        #pragma unroll
        for (int ks = 0; ks < 2; ks++) {
            uint32_t a[2][4];
            #pragma unroll
            for (int mt = 0; mt < 2; mt++)
                LDSM_X4(a[mt][0], a[mt][1], a[mt][2], a[mt][3],
                        sA + aoff + mt * 1280 + ks * 32);
            uint32_t b[8][2];
            #pragma unroll
            for (int np = 0; np < 4; np++) {
                uint32_t r0, r1, r2, r3;
                LDSM_X4(r0, r1, r2, r3, sB + boff + np * 1280 + ks * 32);
                b[np * 2][0]     = r0; b[np * 2][1]     = r1;
                b[np * 2 + 1][0] = r2; b[np * 2 + 1][1] = r3;
            }
            #pragma unroll
            for (int mt = 0; mt < 2; mt++)
                #pragma unroll
                for (int nt = 0; nt < 8; nt++)
                    MMA16816(acc[mt][nt], a[mt], b[nt]);
        }
        // no trailing sync: top-of-loop sync (after wait) protects stage reuse
    }

    // ---------------- epilogue ----------------
    const int mrow0 = row0 + warp_m * 32 + (lane >> 2);
    const int ncb   = col0 + warp_n * 64 + (lane & 3) * 2;

    #pragma unroll
    for (int mt = 0; mt < 2; mt++) {
        #pragma unroll
        for (int half = 0; half < 2; half++) {     // row, row+8
            const int r = mrow0 + mt * 16 + half * 8;
            int mv = 1;
            if (MODE == 1) mv = mask[r];
            #pragma unroll
            for (int nt = 0; nt < 8; nt++) {
                const int ncol = ncb + nt * 8;
                float v0 = acc[mt][nt][half * 2];
                float v1 = acc[mt][nt][half * 2 + 1];
                if (MODE == 0) {
                    if (col0 < FHID) {
                        v0 = silu(v0 + bias1[ncol]);
                        v1 = silu(v1 + bias1[ncol + 1]);
                        *(__half2*)&outh[(size_t)r * FHID + ncol] =
                            __floats2half2_rn(v0, v1);
                    } else {
                        const int a0 = ncol - FHID;
                        float2 o;
                        o.x = silu(v0 + bias2[a0]);
                        o.y = silu(v1 + bias2[a0 + 1]);
                        *(float2*)&outf[(size_t)r * AHID + a0] = o;
                    }
                } else {
                    v0 += bias1[ncol];
                    v1 += bias1[ncol + 1];
                    if (!mv) { v0 = 0.f; v1 = 0.f; }
                    float2 o;
                    o.x = v0 + residual[(size_t)r * FOUT + ncol];
                    o.y = v1 + residual[(size_t)r * FOUT + ncol + 1];
                    *(float2*)&outf[(size_t)r * FOUT + ncol] = o;
                }
            }
        }
    }
}

// ---------------------------------------------------------------------------
// scores[M,4] = g_ah[M,256] @ aw2[256,4] + ab2  (one warp per row)
// ---------------------------------------------------------------------------
__global__ void attn2_kernel(const float* __restrict__ ah,
                             const float* __restrict__ aw2,
                             const float* __restrict__ ab2,
                             float* __restrict__ scores)
{
    const int warp = (blockIdx.x * blockDim.x + threadIdx.x) >> 5;
    const int lane = threadIdx.x & 31;
    if (warp >= MROWS) return;
    const float* a = ah + (size_t)warp * AHID;
    float a0 = 0.f, a1 = 0.f, a2 = 0.f, a3 = 0.f;
    #pragma unroll
    for (int i = 0; i < AHID / 32; i++) {
        int k = lane + i * 32;
        float av = a[k];
        float4 wv = ((const float4*)aw2)[k];
        a0 = fmaf(av, wv.x, a0); a1 = fmaf(av, wv.y, a1);
        a2 = fmaf(av, wv.z, a2); a3 = fmaf(av, wv.w, a3);
    }
    a0 = warp_sum(a0); a1 = warp_sum(a1); a2 = warp_sum(a2); a3 = warp_sum(a3);
    if (lane == 0)
        ((float4*)scores)[warp] =
            make_float4(a0 + ab2[0], a1 + ab2[1], a2 + ab2[2], a3 + ab2[3]);
}

// ---------------------------------------------------------------------------
// Masked softmax over nodes per (graph, head)
// ---------------------------------------------------------------------------
__global__ void softmax_kernel(const float* __restrict__ scores,
                               const int* __restrict__ mask,
                               float* __restrict__ w)
{
    const int b = blockIdx.x;
    const int n = threadIdx.x;
    const int idx = b * NNODES + n;
    const float NEG = -INFINITY;
    const float inv_scale = 1.0f / 16.0f;

    float4 s = ((const float4*)scores)[idx];
    const bool valid = mask[idx] != 0;
    float v0 = valid ? s.x * inv_scale : NEG;
    float v1 = valid ? s.y * inv_scale : NEG;
    float v2 = valid ? s.z * inv_scale : NEG;
    float v3 = valid ? s.w * inv_scale : NEG;

    __shared__ float4 red[NNODES];
    red[n] = make_float4(v0, v1, v2, v3);
    __syncthreads();
    for (int off = 128; off > 0; off >>= 1) {
        if (n < off) {
            float4 a = red[n], c = red[n + off];
            red[n] = make_float4(fmaxf(a.x, c.x), fmaxf(a.y, c.y),
                                 fmaxf(a.z, c.z), fmaxf(a.w, c.w));
        }
        __syncthreads();
    }
    float4 mx = red[0];
    __syncthreads();

    float e0 = valid ? __expf(v0 - mx.x) : 0.f;
    float e1 = valid ? __expf(v1 - mx.y) : 0.f;
    float e2 = valid ? __expf(v2 - mx.z) : 0.f;
    float e3 = valid ? __expf(v3 - mx.w) : 0.f;

    red[n] = make_float4(e0, e1, e2, e3);
    __syncthreads();
    for (int off = 128; off > 0; off >>= 1) {
        if (n < off) {
            float4 a = red[n], c = red[n + off];
            red[n] = make_float4(a.x + c.x, a.y + c.y, a.z + c.z, a.w + c.w);
        }
        __syncthreads();
    }
    float4 sm = red[0];
    ((float4*)w)[idx] = make_float4(e0 / sm.x, e1 / sm.y, e2 / sm.z, e3 / sm.w);
}

// ---------------------------------------------------------------------------
// pooled[b,c] = sum_n new_nodes[b,n,c] * w[b,n,c/64]
// ---------------------------------------------------------------------------
__global__ void pool_kernel(const float* __restrict__ newn,
                            const float* __restrict__ w,
                            float* __restrict__ pooled)
{
    const int b = blockIdx.x;
    const int c = threadIdx.x;
    __shared__ float ws[NNODES * NHEADS];
    ((float4*)ws)[c] = ((const float4*)(w + (size_t)b * NNODES * NHEADS))[c];
    __syncthreads();

    const int h = c >> 6;
    const float* base = newn + (size_t)b * NNODES * FOUT + c;
    float acc = 0.f;
    #pragma unroll 8
    for (int n = 0; n < NNODES; n++)
        acc = fmaf(base[(size_t)n * FOUT], ws[n * NHEADS + h], acc);
    pooled[b * FOUT + c] = acc;
}

// ---------------------------------------------------------------------------
// Launch
// ---------------------------------------------------------------------------
extern "C" void kernel_launch(void* const* d_in, const int* in_sizes, int n_in,
                              void* d_out, int out_size)
{
    const float* nodes = (const float*)d_in[0];
    const float* pe    = (const float*)d_in[1];
    const int*   mask  = (const int*)d_in[2];
    const float* globs = (const float*)d_in[3];
    const float* ln_g  = (const float*)d_in[4];
    const float* ln_b  = (const float*)d_in[5];
    const float* fw1   = (const float*)d_in[6];
    const float* fb1   = (const float*)d_in[7];
    const float* fw2   = (const float*)d_in[8];
    const float* fb2   = (const float*)d_in[9];
    const float* aw1   = (const float*)d_in[10];
    const float* ab1   = (const float*)d_in[11];
    const float* aw2   = (const float*)d_in[12];
    const float* ab2   = (const float*)d_in[13];

    float* out_nodes  = (float*)d_out;
    float* out_pooled = out_nodes + (size_t)MROWS * FOUT;

    __half *p_inp, *p_hid, *p_w1t, *p_w2t;
    float  *p_ah, *p_scores, *p_wsm;
    cudaGetSymbolAddress((void**)&p_inp,    g_inp);
    cudaGetSymbolAddress((void**)&p_hid,    g_hid);
    cudaGetSymbolAddress((void**)&p_ah,     g_ah);
    cudaGetSymbolAddress((void**)&p_scores, g_scores);
    cudaGetSymbolAddress((void**)&p_wsm,    g_wsm);
    cudaGetSymbolAddress((void**)&p_w1t,    g_w1t);
    cudaGetSymbolAddress((void**)&p_w2t,    g_w2t);

    cudaFuncSetAttribute(gemm_mma<0>, cudaFuncAttributeMaxDynamicSharedMemorySize, GSMEM);
    cudaFuncSetAttribute(gemm_mma<1>, cudaFuncAttributeMaxDynamicSharedMemorySize, GSMEM);

    // 1) LN + concat -> g_inp fp16 [M,576]
    prep_kernel<<<MROWS, 128>>>(nodes, pe, globs, ln_g, ln_b, p_inp);

    // 2) weight transposes (fp32 -> fp16, [K,N] -> [N,K])
    wtrans_kernel<<<dim3(40, 18), dim3(32, 8)>>>(fw1, FHID, aw1, AHID, KIN, p_w1t);
    wtrans_kernel<<<dim3(8, 32),  dim3(32, 8)>>>(fw2, FOUT, nullptr, 0, FHID, p_w2t);

    // 3) fused GEMM1: [M,576] @ [576,1280] -> silu -> g_hid fp16 / g_ah fp32
    //    grid.x = col tiles (10) so each wave reuses A strips + all of B in L2
    gemm_mma<0><<<dim3((FHID + AHID) / 128, MROWS / 128), 256, GSMEM>>>(
        p_inp, p_w1t, KIN, fb1, ab1, p_hid, p_ah, nullptr, nullptr);

    // 4) head scores -> softmax weights
    attn2_kernel<<<MROWS / 8, 256>>>(p_ah, aw2, ab2, p_scores);
    softmax_kernel<<<BATCH, NNODES>>>(p_scores, mask, p_wsm);

    // 5) GEMM3: [M,1024] @ [1024,256] + bias + mask + residual -> new_nodes
    gemm_mma<1><<<dim3(FOUT / 128, MROWS / 128), 256, GSMEM>>>(
        p_hid, p_w2t, FHID, fb2, nullptr, nullptr, out_nodes, mask, nodes);

    // 6) attention pooling
    pool_kernel<<<BATCH, 256>>>(out_nodes, p_wsm, out_pooled);
}

// round 7
// speedup vs baseline: 5.4391x; 1.0851x over previous
#include <cuda_runtime.h>
#include <cuda_fp16.h>
#include <math.h>
#include <stdint.h>

// Problem constants
#define BATCH   512
#define NNODES  256
#define MROWS   (BATCH * NNODES)     // 131072
#define FEAT_IN 512
#define GLOB_D  64
#define KIN     576
#define FHID    1024
#define AHID    256
#define FOUT    256
#define NTOT1   (FHID + AHID)        // 1280
#define NHEADS  4
#define LN_EPS  1e-5f

// ---------------------------------------------------------------------------
// Scratch (device globals; no runtime allocation)
// ---------------------------------------------------------------------------
__device__ __half g_inp[(size_t)MROWS * FEAT_IN];      // fp16 LN output [M,512]
__device__ __half g_hid[(size_t)MROWS * FHID];         // fp16 silu hidden [M,1024]
__device__ __half g_ah [(size_t)MROWS * AHID];         // fp16 attn hidden [M,256]
__device__ float  g_scores[(size_t)MROWS * NHEADS];
__device__ float  g_wsm   [(size_t)MROWS * NHEADS];
__device__ __half g_w1t[(size_t)NTOT1 * FEAT_IN];      // [1280,512] (fw1||aw1)^T fp16
__device__ __half g_w2t[(size_t)FOUT * FHID];          // [256,1024] fw2^T fp16
__device__ float  g_ctx1[(size_t)BATCH * NTOT1];       // per-graph ctx contribution

// ---------------------------------------------------------------------------
// PTX helpers (baseline ISA: works at compute_103 target)
// ---------------------------------------------------------------------------
__device__ __forceinline__ uint32_t smem_u32(const void* p) {
    uint32_t a;
    asm("{ .reg .u64 t; cvta.to.shared.u64 t, %1; cvt.u32.u64 %0, t; }"
        : "=r"(a) : "l"(p));
    return a;
}

#define CP_ASYNC16(dst, src) \
    asm volatile("cp.async.cg.shared.global [%0], [%1], 16;" \
        :: "r"(dst), "l"(src))
#define CP_COMMIT()  asm volatile("cp.async.commit_group;" ::: "memory")
#define CP_WAIT2()   asm volatile("cp.async.wait_group 2;" ::: "memory")

#define LDSM_X4(r0, r1, r2, r3, addr) \
    asm volatile("ldmatrix.sync.aligned.m8n8.x4.shared.b16 {%0,%1,%2,%3}, [%4];" \
        : "=r"(r0), "=r"(r1), "=r"(r2), "=r"(r3) : "r"(addr))

#define MMA16816(c, a, b) \
    asm volatile("mma.sync.aligned.m16n8k16.row.col.f32.f16.f16.f32 " \
        "{%0,%1,%2,%3}, {%4,%5,%6,%7}, {%8,%9}, {%0,%1,%2,%3};" \
        : "+f"((c)[0]), "+f"((c)[1]), "+f"((c)[2]), "+f"((c)[3]) \
        : "r"((a)[0]), "r"((a)[1]), "r"((a)[2]), "r"((a)[3]), \
          "r"((b)[0]), "r"((b)[1]))

__device__ __forceinline__ float warp_sum(float v) {
    #pragma unroll
    for (int o = 16; o > 0; o >>= 1) v += __shfl_xor_sync(0xffffffffu, v, o);
    return v;
}

__device__ __forceinline__ float silu(float v) {
    return __fdividef(v, 1.0f + __expf(-v));
}

// ---------------------------------------------------------------------------
// Kernel 1: LayerNorm(concat(nodes, pe)) -> g_inp fp16 [M,512]
// ---------------------------------------------------------------------------
__global__ void prep_kernel(const float* __restrict__ nodes,
                            const float* __restrict__ pe,
                            const float* __restrict__ ln_g,
                            const float* __restrict__ ln_b,
                            __half* __restrict__ inp)
{
    const int row = blockIdx.x;
    const int t   = threadIdx.x;          // 0..127

    float4 v = (t < 64)
        ? ((const float4*)nodes)[(size_t)row * 64 + t]
        : ((const float4*)pe)   [(size_t)row * 64 + (t - 64)];

    float s  = v.x + v.y + v.z + v.w;
    float sq = v.x*v.x + v.y*v.y + v.z*v.z + v.w*v.w;

    __shared__ float ssum[4], ssq[4];
    __shared__ float s_mu, s_rstd;
    const int lane = t & 31, wid = t >> 5;
    float ws = warp_sum(s), wq = warp_sum(sq);
    if (lane == 0) { ssum[wid] = ws; ssq[wid] = wq; }
    __syncthreads();
    if (t == 0) {
        float S = ssum[0] + ssum[1] + ssum[2] + ssum[3];
        float Q = ssq[0]  + ssq[1]  + ssq[2]  + ssq[3];
        float mu  = S * (1.0f / FEAT_IN);
        float var = Q * (1.0f / FEAT_IN) - mu * mu;
        s_mu = mu; s_rstd = rsqrtf(var + LN_EPS);
    }
    __syncthreads();
    const float mu = s_mu, rstd = s_rstd;

    float4 g4 = ((const float4*)ln_g)[t];
    float4 b4 = ((const float4*)ln_b)[t];
    float o0 = (v.x - mu) * rstd * g4.x + b4.x;
    float o1 = (v.y - mu) * rstd * g4.y + b4.y;
    float o2 = (v.z - mu) * rstd * g4.z + b4.z;
    float o3 = (v.w - mu) * rstd * g4.w + b4.w;

    __half* dst = inp + (size_t)row * FEAT_IN + t * 4;
    *(__half2*)(dst)     = __floats2half2_rn(o0, o1);
    *(__half2*)(dst + 2) = __floats2half2_rn(o2, o3);
}

// ---------------------------------------------------------------------------
// Per-graph ctx contribution: ctx1[b,n] = sum_j globs[b,j] * W[512+j, n]
// (n<1024 -> fw1, else aw1). fp32. One block per graph.
// ---------------------------------------------------------------------------
__global__ void ctx_kernel(const float* __restrict__ globs,
                           const float* __restrict__ fw1,
                           const float* __restrict__ aw1,
                           float* __restrict__ ctx1)
{
    __shared__ float gs[GLOB_D];
    const int b = blockIdx.x;
    if (threadIdx.x < GLOB_D) gs[threadIdx.x] = globs[b * GLOB_D + threadIdx.x];
    __syncthreads();
    for (int n = threadIdx.x; n < NTOT1; n += blockDim.x) {
        float acc = 0.f;
        if (n < FHID) {
            #pragma unroll 8
            for (int j = 0; j < GLOB_D; j++)
                acc = fmaf(gs[j], fw1[(size_t)(FEAT_IN + j) * FHID + n], acc);
        } else {
            #pragma unroll 8
            for (int j = 0; j < GLOB_D; j++)
                acc = fmaf(gs[j], aw1[(size_t)(FEAT_IN + j) * AHID + (n - FHID)], acc);
        }
        ctx1[(size_t)b * NTOT1 + n] = acc;
    }
}

// ---------------------------------------------------------------------------
// Weight transpose + fp16 cast: Wt[n,k] = (n<N1 ? W1[k,n] : W2[k,n-N1]), k<K
// ---------------------------------------------------------------------------
__global__ void wtrans_kernel(const float* __restrict__ W1, int N1, int ld1,
                              const float* __restrict__ W2, int N2, int ld2,
                              int K, __half* __restrict__ Wt)
{
    __shared__ float tile[32][33];
    const int nb = blockIdx.x * 32, kb = blockIdx.y * 32;
    const int tx = threadIdx.x, ty = threadIdx.y;
    const int Ntot = N1 + N2;
    for (int i = ty; i < 32; i += 8) {
        int k = kb + i, n = nb + tx;
        float v = 0.f;
        if (k < K && n < Ntot)
            v = (n < N1) ? W1[(size_t)k * ld1 + n] : W2[(size_t)k * ld2 + (n - N1)];
        tile[i][tx] = v;
    }
    __syncthreads();
    for (int i = ty; i < 32; i += 8) {
        int n = nb + i, k = kb + tx;
        if (n < Ntot && k < K)
            Wt[(size_t)n * K + k] = __float2half_rn(tile[tx][i]);
    }
}

// ---------------------------------------------------------------------------
// HGEMM via mma.sync m16n8k16: C[M,N] = A[M,K] @ Bt[N,K]^T (+epilogue)
// CTA tile 128x128, BK=32, 4-stage cp.async pipeline, 8 warps (4m x 2n),
// warp tile 32x64. Smem row stride 40 halfs (80B) -> conflict-free ldmatrix.
// MODE 0 (GEMM1): silu(x + bias + ctx); ncol<1024 -> fp16 outh[.,1024];
//                 ncol>=1024 -> fp16 outa[.,256] with bias2.
// MODE 1 (GEMM3): x + bias1, zero-if-!mask, +residual -> fp32 outf[.,256].
// ---------------------------------------------------------------------------
#define NSTAGE    4
#define GSTAGE_B  20480               // (128*40*2) * 2 tiles
#define GSMEM     (NSTAGE * GSTAGE_B) // 81920

template<int MODE>
__global__ __launch_bounds__(256, 2) void gemm_mma(
    const __half* __restrict__ A, const __half* __restrict__ Bt, int K,
    const float* __restrict__ bias1, const float* __restrict__ bias2,
    const float* __restrict__ ctx1,
    __half* __restrict__ outh, __half* __restrict__ outa,
    float* __restrict__ outf,
    const int* __restrict__ mask, const float* __restrict__ residual)
{
    extern __shared__ char smem[];
    const uint32_t sbase = smem_u32(smem);
    const int tid    = threadIdx.x;
    const int wid    = tid >> 5;
    const int lane   = tid & 31;
    const int warp_m = wid & 3;        // 4 groups of 32 rows
    const int warp_n = wid >> 2;       // 2 groups of 64 cols
    const int row0   = blockIdx.y * 128;
    const int col0   = blockIdx.x * 128;
    const int iters  = K >> 5;

    // per-thread cp.async source/dest mapping (2 x 16B per tile per stage)
    const int ldr = tid >> 2;              // 0..63  (row base; +64 for i=1)
    const int ldk = (tid & 3) * 8;         // k-offset in halfs (16B units)

    float acc[2][8][4];
    #pragma unroll
    for (int mt = 0; mt < 2; mt++)
        #pragma unroll
        for (int nt = 0; nt < 8; nt++)
            #pragma unroll
            for (int j = 0; j < 4; j++) acc[mt][nt][j] = 0.f;

    // ldmatrix lane-derived offsets
    const int lm = lane & 15, lq = lane >> 4;
    const uint32_t aoff = ((warp_m * 32 + lm) * 40 + lq * 8) * 2;
    const int bn = (lane >> 4) * 8 + (lane & 7);
    const int bk = ((lane >> 3) & 1) * 8;
    const uint32_t boff = ((warp_n * 64 + bn) * 40 + bk) * 2;

    auto load_stage = [&](int s, int kk) {
        const uint32_t dA = sbase + s * GSTAGE_B;
        const uint32_t dB = dA + 10240;
        #pragma unroll
        for (int i = 0; i < 2; i++) {
            const int r = ldr + i * 64;
            const uint32_t soff = (r * 40 + ldk) * 2;
            CP_ASYNC16(dA + soff, &A [(size_t)(row0 + r) * K + kk + ldk]);
            CP_ASYNC16(dB + soff, &Bt[(size_t)(col0 + r) * K + kk + ldk]);
        }
    };

    load_stage(0, 0);  CP_COMMIT();
    load_stage(1, 32); CP_COMMIT();
    load_stage(2, 64); CP_COMMIT();

    for (int i = 0; i < iters; i++) {
        CP_WAIT2();
        __syncthreads();
        if (i + 3 < iters) load_stage((i + 3) % NSTAGE, (i + 3) * 32);
        CP_COMMIT();

        const int s = i % NSTAGE;
        const uint32_t sA = sbase + s * GSTAGE_B;
        const uint32_t sB = sA + 10240;

        #pragma unroll
        for (int ks = 0; ks < 2; ks++) {
            uint32_t a[2][4];
            #pragma unroll
            for (int mt = 0; mt < 2; mt++)
                LDSM_X4(a[mt][0], a[mt][1], a[mt][2], a[mt][3],
                        sA + aoff + mt * 1280 + ks * 32);
            uint32_t b[8][2];
            #pragma unroll
            for (int np = 0; np < 4; np++) {
                uint32_t r0, r1, r2, r3;
                LDSM_X4(r0, r1, r2, r3, sB + boff + np * 1280 + ks * 32);
                b[np * 2][0]     = r0; b[np * 2][1]     = r1;
                b[np * 2 + 1][0] = r2; b[np * 2 + 1][1] = r3;
            }
            #pragma unroll
            for (int mt = 0; mt < 2; mt++)
                #pragma unroll
                for (int nt = 0; nt < 8; nt++)
                    MMA16816(acc[mt][nt], a[mt], b[nt]);
        }
        // top-of-loop sync (after wait) protects stage reuse
    }

    // ---------------- epilogue ----------------
    const int mrow0 = row0 + warp_m * 32 + (lane >> 2);
    const int ncb   = col0 + warp_n * 64 + (lane & 3) * 2;

    #pragma unroll
    for (int mt = 0; mt < 2; mt++) {
        #pragma unroll
        for (int half = 0; half < 2; half++) {     // row, row+8
            const int r = mrow0 + mt * 16 + half * 8;
            const int bg = r >> 8;                 // graph index
            int mv = 1;
            if (MODE == 1) mv = mask[r];
            #pragma unroll
            for (int nt = 0; nt < 8; nt++) {
                const int ncol = ncb + nt * 8;
                float v0 = acc[mt][nt][half * 2];
                float v1 = acc[mt][nt][half * 2 + 1];
                if (MODE == 0) {
                    const float c0 = ctx1[(size_t)bg * NTOT1 + ncol];
                    const float c1 = ctx1[(size_t)bg * NTOT1 + ncol + 1];
                    if (ncol < FHID) {
                        v0 = silu(v0 + bias1[ncol]     + c0);
                        v1 = silu(v1 + bias1[ncol + 1] + c1);
                        *(__half2*)&outh[(size_t)r * FHID + ncol] =
                            __floats2half2_rn(v0, v1);
                    } else {
                        const int a0 = ncol - FHID;
                        v0 = silu(v0 + bias2[a0]     + c0);
                        v1 = silu(v1 + bias2[a0 + 1] + c1);
                        *(__half2*)&outa[(size_t)r * AHID + a0] =
                            __floats2half2_rn(v0, v1);
                    }
                } else {
                    v0 += bias1[ncol];
                    v1 += bias1[ncol + 1];
                    if (!mv) { v0 = 0.f; v1 = 0.f; }
                    float2 o;
                    o.x = v0 + residual[(size_t)r * FOUT + ncol];
                    o.y = v1 + residual[(size_t)r * FOUT + ncol + 1];
                    *(float2*)&outf[(size_t)r * FOUT + ncol] = o;
                }
            }
        }
    }
}

// ---------------------------------------------------------------------------
// scores[M,4] = g_ah[M,256] @ aw2[256,4] + ab2  (one warp per row, fp16 in)
// ---------------------------------------------------------------------------
__global__ void attn2_kernel(const __half* __restrict__ ah,
                             const float* __restrict__ aw2,
                             const float* __restrict__ ab2,
                             float* __restrict__ scores)
{
    const int warp = (blockIdx.x * blockDim.x + threadIdx.x) >> 5;
    const int lane = threadIdx.x & 31;
    if (warp >= MROWS) return;
    const __half2* a2 = (const __half2*)(ah + (size_t)warp * AHID);
    float a0 = 0.f, a1 = 0.f, a2s = 0.f, a3 = 0.f;
    #pragma unroll
    for (int i = 0; i < 4; i++) {
        const int k2 = i * 32 + lane;      // half2 index (k = 2*k2, 2*k2+1)
        __half2 h = a2[k2];
        float f0 = __low2float(h), f1 = __high2float(h);
        float4 w0 = ((const float4*)aw2)[2 * k2];
        float4 w1 = ((const float4*)aw2)[2 * k2 + 1];
        a0  = fmaf(f0, w0.x, fmaf(f1, w1.x, a0));
        a1  = fmaf(f0, w0.y, fmaf(f1, w1.y, a1));
        a2s = fmaf(f0, w0.z, fmaf(f1, w1.z, a2s));
        a3  = fmaf(f0, w0.w, fmaf(f1, w1.w, a3));
    }
    a0 = warp_sum(a0); a1 = warp_sum(a1); a2s = warp_sum(a2s); a3 = warp_sum(a3);
    if (lane == 0)
        ((float4*)scores)[warp] =
            make_float4(a0 + ab2[0], a1 + ab2[1], a2s + ab2[2], a3 + ab2[3]);
}

// ---------------------------------------------------------------------------
// Masked softmax over nodes per (graph, head)
// ---------------------------------------------------------------------------
__global__ void softmax_kernel(const float* __restrict__ scores,
                               const int* __restrict__ mask,
                               float* __restrict__ w)
{
    const int b = blockIdx.x;
    const int n = threadIdx.x;
    const int idx = b * NNODES + n;
    const float NEG = -INFINITY;
    const float inv_scale = 1.0f / 16.0f;

    float4 s = ((const float4*)scores)[idx];
    const bool valid = mask[idx] != 0;
    float v0 = valid ? s.x * inv_scale : NEG;
    float v1 = valid ? s.y * inv_scale : NEG;
    float v2 = valid ? s.z * inv_scale : NEG;
    float v3 = valid ? s.w * inv_scale : NEG;

    __shared__ float4 red[NNODES];
    red[n] = make_float4(v0, v1, v2, v3);
    __syncthreads();
    for (int off = 128; off > 0; off >>= 1) {
        if (n < off) {
            float4 a = red[n], c = red[n + off];
            red[n] = make_float4(fmaxf(a.x, c.x), fmaxf(a.y, c.y),
                                 fmaxf(a.z, c.z), fmaxf(a.w, c.w));
        }
        __syncthreads();
    }
    float4 mx = red[0];
    __syncthreads();

    float e0 = valid ? __expf(v0 - mx.x) : 0.f;
    float e1 = valid ? __expf(v1 - mx.y) : 0.f;
    float e2 = valid ? __expf(v2 - mx.z) : 0.f;
    float e3 = valid ? __expf(v3 - mx.w) : 0.f;

    red[n] = make_float4(e0, e1, e2, e3);
    __syncthreads();
    for (int off = 128; off > 0; off >>= 1) {
        if (n < off) {
            float4 a = red[n], c = red[n + off];
            red[n] = make_float4(a.x + c.x, a.y + c.y, a.z + c.z, a.w + c.w);
        }
        __syncthreads();
    }
    float4 sm = red[0];
    ((float4*)w)[idx] = make_float4(e0 / sm.x, e1 / sm.y, e2 / sm.z, e3 / sm.w);
}

// ---------------------------------------------------------------------------
// pooled[b,c] = sum_n new_nodes[b,n,c] * w[b,n,c/64]
// ---------------------------------------------------------------------------
__global__ void pool_kernel(const float* __restrict__ newn,
                            const float* __restrict__ w,
                            float* __restrict__ pooled)
{
    const int b = blockIdx.x;
    const int c = threadIdx.x;
    __shared__ float ws[NNODES * NHEADS];
    ((float4*)ws)[c] = ((const float4*)(w + (size_t)b * NNODES * NHEADS))[c];
    __syncthreads();

    const int h = c >> 6;
    const float* base = newn + (size_t)b * NNODES * FOUT + c;
    float acc = 0.f;
    #pragma unroll 8
    for (int n = 0; n < NNODES; n++)
        acc = fmaf(base[(size_t)n * FOUT], ws[n * NHEADS + h], acc);
    pooled[b * FOUT + c] = acc;
}

// ---------------------------------------------------------------------------
// Launch
// ---------------------------------------------------------------------------
extern "C" void kernel_launch(void* const* d_in, const int* in_sizes, int n_in,
                              void* d_out, int out_size)
{
    const float* nodes = (const float*)d_in[0];
    const float* pe    = (const float*)d_in[1];
    const int*   mask  = (const int*)d_in[2];
    const float* globs = (const float*)d_in[3];
    const float* ln_g  = (const float*)d_in[4];
    const float* ln_b  = (const float*)d_in[5];
    const float* fw1   = (const float*)d_in[6];
    const float* fb1   = (const float*)d_in[7];
    const float* fw2   = (const float*)d_in[8];
    const float* fb2   = (const float*)d_in[9];
    const float* aw1   = (const float*)d_in[10];
    const float* ab1   = (const float*)d_in[11];
    const float* aw2   = (const float*)d_in[12];
    const float* ab2   = (const float*)d_in[13];

    float* out_nodes  = (float*)d_out;
    float* out_pooled = out_nodes + (size_t)MROWS * FOUT;

    __half *p_inp, *p_hid, *p_ah, *p_w1t, *p_w2t;
    float  *p_scores, *p_wsm, *p_ctx1;
    cudaGetSymbolAddress((void**)&p_inp,    g_inp);
    cudaGetSymbolAddress((void**)&p_hid,    g_hid);
    cudaGetSymbolAddress((void**)&p_ah,     g_ah);
    cudaGetSymbolAddress((void**)&p_scores, g_scores);
    cudaGetSymbolAddress((void**)&p_wsm,    g_wsm);
    cudaGetSymbolAddress((void**)&p_w1t,    g_w1t);
    cudaGetSymbolAddress((void**)&p_w2t,    g_w2t);
    cudaGetSymbolAddress((void**)&p_ctx1,   g_ctx1);

    cudaFuncSetAttribute(gemm_mma<0>, cudaFuncAttributeMaxDynamicSharedMemorySize, GSMEM);
    cudaFuncSetAttribute(gemm_mma<1>, cudaFuncAttributeMaxDynamicSharedMemorySize, GSMEM);
    cudaFuncSetAttribute(gemm_mma<0>, cudaFuncAttributePreferredSharedMemoryCarveout, 100);
    cudaFuncSetAttribute(gemm_mma<1>, cudaFuncAttributePreferredSharedMemoryCarveout, 100);

    // 1) LN + concat -> g_inp fp16 [M,512]
    prep_kernel<<<MROWS, 128>>>(nodes, pe, ln_g, ln_b, p_inp);

    // 2) per-graph ctx contribution (fp32), weight transposes (fp32->fp16)
    ctx_kernel<<<BATCH, 256>>>(globs, fw1, aw1, p_ctx1);
    wtrans_kernel<<<dim3(40, 16), dim3(32, 8)>>>(fw1, FHID, FHID, aw1, AHID, AHID,
                                                 FEAT_IN, p_w1t);
    wtrans_kernel<<<dim3(8, 32),  dim3(32, 8)>>>(fw2, FOUT, FOUT, nullptr, 0, 0,
                                                 FHID, p_w2t);

    // 3) fused GEMM1: [M,512] @ [512,1280] + ctx -> silu -> g_hid / g_ah (fp16)
    gemm_mma<0><<<dim3(NTOT1 / 128, MROWS / 128), 256, GSMEM>>>(
        p_inp, p_w1t, FEAT_IN, fb1, ab1, p_ctx1, p_hid, p_ah,
        nullptr, nullptr, nullptr);

    // 4) head scores -> softmax weights
    attn2_kernel<<<MROWS / 8, 256>>>(p_ah, aw2, ab2, p_scores);
    softmax_kernel<<<BATCH, NNODES>>>(p_scores, mask, p_wsm);

    // 5) GEMM3: [M,1024] @ [1024,256] + bias + mask + residual -> new_nodes
    gemm_mma<1><<<dim3(FOUT / 128, MROWS / 128), 256, GSMEM>>>(
        p_hid, p_w2t, FHID, fb2, nullptr, nullptr, nullptr, nullptr,
        out_nodes, mask, nodes);

    // 6) attention pooling
    pool_kernel<<<BATCH, 256>>>(out_nodes, p_wsm, out_pooled);
}